// round 1
// baseline (speedup 1.0000x reference)
#include <cuda_runtime.h>

#define RH 256
#define RW 256
#define NPIX (RH * RW)
#define REPS 1e-8f

// Z-buffer keys: (depth_bits << 32) | face_index. Sized for up to 4 batches.
static __device__ unsigned long long g_zkey[4 * NPIX];

struct FS {
    float x0, y0, x1, y1, x2, y2;
    float z0, z1, z2;
    float A0, B0, A1, B1, inv;
    int i0, i1, i2;
    bool valid;
};

// Reference arithmetic, reproduced bitwise: all ops round-to-nearest, NO fma
// contraction (explicit __f*_rn intrinsics), same evaluation order as the JAX code.
__device__ __forceinline__ FS face_setup(const float* __restrict__ verts,
                                         const int* __restrict__ faces,
                                         int n, int V, int f) {
    FS s;
    s.i0 = faces[3 * f + 0];
    s.i1 = faces[3 * f + 1];
    s.i2 = faces[3 * f + 2];
    const float* base = verts + (size_t)n * (size_t)V * 3;
    float vx0 = base[3 * s.i0 + 0], vy0 = base[3 * s.i0 + 1], vz0 = base[3 * s.i0 + 2];
    float vx1 = base[3 * s.i1 + 0], vy1 = base[3 * s.i1 + 1], vz1 = base[3 * s.i1 + 2];
    float vx2 = base[3 * s.i2 + 0], vy2 = base[3 * s.i2 + 1], vz2 = base[3 * s.i2 + 2];
    s.z0 = vz0; s.z1 = vz1; s.z2 = vz2;
    s.x0 = __fdiv_rn(vx0, vz0); s.y0 = __fdiv_rn(vy0, vz0);
    s.x1 = __fdiv_rn(vx1, vz1); s.y1 = __fdiv_rn(vy1, vz1);
    s.x2 = __fdiv_rn(vx2, vz2); s.y2 = __fdiv_rn(vy2, vz2);
    s.A0 = __fsub_rn(s.y1, s.y2);
    s.B0 = __fsub_rn(s.x2, s.x1);
    s.A1 = __fsub_rn(s.y2, s.y0);
    s.B1 = __fsub_rn(s.x0, s.x2);
    float denom = __fadd_rn(__fmul_rn(s.A0, __fsub_rn(s.x0, s.x2)),
                            __fmul_rn(s.B0, __fsub_rn(s.y0, s.y2)));
    bool nz = fabsf(denom) > REPS;
    s.valid = nz && (vz0 > 0.0f) && (vz1 > 0.0f) && (vz2 > 0.0f);
    s.inv = __fdiv_rn(1.0f, nz ? denom : 1.0f);
    return s;
}

__device__ __forceinline__ void eval_w(const FS& s, float xf, float yf,
                                       float& w0, float& w1, float& w2) {
    float dx = __fsub_rn(xf, s.x2);
    float dy = __fsub_rn(yf, s.y2);
    w0 = __fmul_rn(__fadd_rn(__fmul_rn(s.A0, dx), __fmul_rn(s.B0, dy)), s.inv);
    w1 = __fmul_rn(__fadd_rn(__fmul_rn(s.A1, dx), __fmul_rn(s.B1, dy)), s.inv);
    w2 = __fsub_rn(__fsub_rn(1.0f, w0), w1);
}

__global__ void clear_kernel(int total) {
    int i = blockIdx.x * blockDim.x + threadIdx.x;
    if (i < total) g_zkey[i] = ~0ULL;
}

// One warp per (batch, face); one bbox row per lane; conservative per-row
// x-interval from the three half-planes, exact test inside.
__global__ void raster_kernel(const float* __restrict__ verts,
                              const int* __restrict__ faces,
                              int N, int V, int F) {
    int gw = (blockIdx.x * blockDim.x + threadIdx.x) >> 5;
    int lane = threadIdx.x & 31;
    if (gw >= N * F) return;
    int n = gw / F;
    int f = gw - n * F;

    FS s = face_setup(verts, faces, n, V, f);
    if (!s.valid) return;

    float minx = fminf(s.x0, fminf(s.x1, s.x2));
    float maxx = fmaxf(s.x0, fmaxf(s.x1, s.x2));
    float miny = fminf(s.y0, fminf(s.y1, s.y2));
    float maxy = fmaxf(s.y0, fmaxf(s.y1, s.y2));
    int xlo = max(0, (int)ceilf(minx) - 1);
    int xhi = min(RW - 1, (int)floorf(maxx) + 1);
    int ylo = max(0, (int)ceilf(miny) - 1);
    int yhi = min(RH - 1, (int)floorf(maxy) + 1);
    if (xlo > xhi || ylo > yhi) return;

    float zminf = fminf(s.z0, fminf(s.z1, s.z2));
    unsigned long long candmin =
        ((unsigned long long)__float_as_uint(zminf) << 32) | (unsigned int)f;
    unsigned long long* zb = g_zkey + (size_t)n * NPIX;

    // w_k(x) along a row: a_k * x + b_k  (approximate; only used for a
    // conservative interval, widened by 1 px; exact test follows inside).
    float a0 = s.A0 * s.inv;
    float a1 = s.A1 * s.inv;
    float a2 = -(a0 + a1);

    for (int y = ylo + lane; y <= yhi; y += 32) {
        float yf = (float)y;
        float dy = yf - s.y2;
        float b0 = (s.B0 * dy - s.A0 * s.x2) * s.inv;
        float b1 = (s.B1 * dy - s.A1 * s.x2) * s.inv;
        float b2 = 1.0f - b0 - b1;

        float lo = (float)xlo, hi = (float)xhi;
        bool empty = false;
        if (a0 > 0.0f)       lo = fmaxf(lo, -b0 / a0);
        else if (a0 < 0.0f)  hi = fminf(hi, -b0 / a0);
        else if (b0 < 0.0f)  empty = true;
        if (a1 > 0.0f)       lo = fmaxf(lo, -b1 / a1);
        else if (a1 < 0.0f)  hi = fminf(hi, -b1 / a1);
        else if (b1 < 0.0f)  empty = true;
        if (a2 > 0.0f)       lo = fmaxf(lo, -b2 / a2);
        else if (a2 < 0.0f)  hi = fminf(hi, -b2 / a2);
        else if (b2 < 0.0f)  empty = true;
        if (empty) continue;

        int xs = max(xlo, (int)ceilf(lo) - 1);
        int xe = min(xhi, (int)floorf(hi) + 1);
        if (xs > xe) continue;

        unsigned long long* zrow = zb + y * RW;
        int x = xs;
        while (x <= xe) {
            int m = min(4, xe - x + 1);
            unsigned long long cur[4];
#pragma unroll
            for (int j = 0; j < 4; ++j)
                if (j < m) cur[j] = zrow[x + j];
#pragma unroll
            for (int j = 0; j < 4; ++j) {
                if (j >= m) break;
                // Early reject: depth at any covered pixel >= min(z0,z1,z2),
                // so this face cannot beat cur[j] if cur[j] <= candmin.
                if (cur[j] <= candmin) continue;
                float xf = (float)(x + j);
                float w0, w1, w2;
                eval_w(s, xf, (float)y, w0, w1, w2);
                if (fminf(fminf(w0, w1), w2) >= 0.0f) {
                    float depth = __fadd_rn(
                        __fadd_rn(__fmul_rn(w0, s.z0), __fmul_rn(w1, s.z1)),
                        __fmul_rn(w2, s.z2));
                    if (depth > 0.0f) {
                        unsigned long long key =
                            ((unsigned long long)__float_as_uint(depth) << 32) |
                            (unsigned int)f;
                        if (key < cur[j]) atomicMin(&zrow[x + j], key);
                    }
                }
            }
            x += 4;
        }
    }
}

__global__ void resolve_kernel(const float* __restrict__ verts,
                               const float* __restrict__ colors,
                               const int* __restrict__ faces,
                               float* __restrict__ out,
                               int N, int V) {
    int idx = blockIdx.x * blockDim.x + threadIdx.x;
    int total = N * NPIX;
    if (idx >= total) return;
    int n = idx / NPIX;
    int pix = idx - n * NPIX;
    int y = pix >> 8;
    int x = pix & 255;

    unsigned long long key = g_zkey[idx];
    float res[8];
    bool anypos = false;
    if (key != ~0ULL) {
        int f = (int)(unsigned int)(key & 0xffffffffULL);
        FS s = face_setup(verts, faces, n, V, f);
        float w0, w1, w2;
        eval_w(s, (float)x, (float)y, w0, w1, w2);
        const float* cb = colors + (size_t)n * (size_t)V * 8;
        const float* c0 = cb + (size_t)s.i0 * 8;
        const float* c1 = cb + (size_t)s.i1 * 8;
        const float* c2 = cb + (size_t)s.i2 * 8;
#pragma unroll
        for (int ch = 0; ch < 8; ++ch) {
            float c = __fadd_rn(
                __fadd_rn(__fmul_rn(w0, c0[ch]), __fmul_rn(w1, c1[ch])),
                __fmul_rn(w2, c2[ch]));
            res[ch] = c;
            anypos = anypos || (c > 0.0f);
        }
    }
#pragma unroll
    for (int ch = 0; ch < 8; ++ch) {
        float v = anypos ? res[ch] : 0.0f;
        out[(((size_t)n * 8 + ch) << 16) + pix] = v;
    }
}

extern "C" void kernel_launch(void* const* d_in, const int* in_sizes, int n_in,
                              void* d_out, int out_size) {
    const float* verts = (const float*)d_in[0];
    const float* colors = (const float*)d_in[1];
    const int* faces = (const int*)d_in[2];
    float* out = (float*)d_out;

    int F = in_sizes[2] / 3;
    int N = out_size / (8 * NPIX);
    if (N < 1) N = 1;
    if (N > 4) N = 4;
    int V = (in_sizes[0] / 3) / N;

    int totalPix = N * NPIX;
    clear_kernel<<<(totalPix + 255) / 256, 256>>>(totalPix);

    int warps = N * F;
    int threads = warps * 32;
    raster_kernel<<<(threads + 255) / 256, 256>>>(verts, faces, N, V, F);

    resolve_kernel<<<(totalPix + 127) / 128, 128>>>(verts, colors, faces, out, N, V);
}